// round 16
// baseline (speedup 1.0000x reference)
#include <cuda_runtime.h>
#include <math_constants.h>
#include <cstdint>

#define BB 4
#define TT 2048
#define CC 1024
#define HH 16
#define DD 64
#define BTOT (BB*TT)          // 8192 rows

// Scratch (allocation-free rule: __device__ globals)
__device__ float g_qkv[(size_t)BTOT * 3 * CC];   // [B*T, 3C]  (tf32-rounded)
__device__ float g_attn[(size_t)BTOT * CC];      // [B*T, C]   (tf32-rounded)
__device__ float g_x [(size_t)BTOT * CC];        // hidden, tf32-rounded
__device__ float g_w1[(size_t)CC * 3 * CC];      // qkv_w, tf32-rounded
__device__ float g_w2[(size_t)CC * CC];          // o_w, tf32-rounded

extern __shared__ char dynsmem[];

__device__ __forceinline__ unsigned f2tf32(float x) {
    unsigned y;
    asm("cvt.rna.tf32.f32 %0, %1;" : "=r"(y) : "f"(x));
    return y;
}

__device__ __forceinline__ void mma_tf32(float d[4], const unsigned a[4], const unsigned b[2]) {
    asm volatile(
        "mma.sync.aligned.m16n8k8.row.col.f32.tf32.tf32.f32 "
        "{%0,%1,%2,%3}, {%4,%5,%6,%7}, {%8,%9}, {%0,%1,%2,%3};"
        : "+f"(d[0]), "+f"(d[1]), "+f"(d[2]), "+f"(d[3])
        : "r"(a[0]), "r"(a[1]), "r"(a[2]), "r"(a[3]), "r"(b[0]), "r"(b[1]));
}

__device__ __forceinline__ void cp_async16(void* smem_dst, const void* gsrc) {
    unsigned sa = (unsigned)__cvta_generic_to_shared(smem_dst);
    asm volatile("cp.async.ca.shared.global [%0], [%1], 16;" :: "r"(sa), "l"(gsrc));
}

// ---------------------------------------------------------------------------
// Pre-pass: fp32 -> tf32-rounded fp32 (vectorized)
// ---------------------------------------------------------------------------
__global__ void cvt_tf32_kernel(const float4* __restrict__ in, float4* __restrict__ out, int n4)
{
    int i = blockIdx.x * blockDim.x + threadIdx.x;
    if (i < n4) {
        float4 v = in[i];
        uint4 r;
        r.x = f2tf32(v.x); r.y = f2tf32(v.y);
        r.z = f2tf32(v.z); r.w = f2tf32(v.w);
        *(uint4*)&out[i] = r;
    }
}

// ---------------------------------------------------------------------------
// TF32 GEMM v2: 128x256 block tile, BK=16, 256 threads (8 warps, 2x4 grid),
// 64x64 warp tile. cp.async double-buffered. Inputs pre-converted to tf32.
// out[M,N] = A[M,K] @ W[K,N] + bias[N].  M%128==0, N%256==0, K%16==0.
// A smem row-major stride 20 (banks 20g+t), B k-major stride 264 (8t+g).
// Dynamic smem: 2*(128*20 + 16*264)*4 = 54,272 B.
// ---------------------------------------------------------------------------
#define ASTR 20
#define BSTR 264
#define GEMM_SMEM (2 * (128 * ASTR + 16 * BSTR) * 4)

template<bool ROUND>
__global__ __launch_bounds__(256)
void gemm_tf32_v2(const float* __restrict__ A, const float* __restrict__ W,
                  const float* __restrict__ bias, float* __restrict__ out,
                  int M, int N, int K)
{
    unsigned* As[2];
    unsigned* Bs[2];
    As[0] = (unsigned*)dynsmem;
    As[1] = As[0] + 128 * ASTR;
    Bs[0] = As[1] + 128 * ASTR;
    Bs[1] = Bs[0] + 16 * BSTR;

    const int tid  = threadIdx.x;
    const int lane = tid & 31;
    const int warp = tid >> 5;
    const int g = lane >> 2;
    const int t = lane & 3;
    const int row0 = blockIdx.y * 128;
    const int col0 = blockIdx.x * 256;

    const int wm = (warp >> 2) * 64;    // 0 or 64
    const int wn = (warp & 3) * 64;     // 0,64,128,192

    const int ntiles = K >> 4;

    // A: 512 chunks of 16B -> 2/thread; B: 1024 chunks -> 4/thread
    const int a_row = tid >> 2, a_kc = (tid & 3) * 4;        // rows 0..63 (+64)
    const int b_row = tid >> 6, b_c  = (tid & 63) * 4;       // rows 0..3 (+4,+8,+12)

    #define LOAD_STAGE(kt, slot) do {                                              \
        const int k0_ = (kt) << 4;                                                 \
        cp_async16(&As[slot][(a_row)      * ASTR + a_kc],                          \
                   A + (size_t)(row0 + a_row)      * K + k0_ + a_kc);              \
        cp_async16(&As[slot][(a_row + 64) * ASTR + a_kc],                          \
                   A + (size_t)(row0 + a_row + 64) * K + k0_ + a_kc);              \
        _Pragma("unroll")                                                          \
        for (int i_ = 0; i_ < 4; i_++) {                                           \
            const int r_ = b_row + 4 * i_;                                         \
            cp_async16(&Bs[slot][r_ * BSTR + b_c],                                 \
                       W + (size_t)(k0_ + r_) * N + col0 + b_c);                   \
        }                                                                          \
        asm volatile("cp.async.commit_group;" ::: "memory");                       \
    } while (0)

    float d[4][8][4];
    #pragma unroll
    for (int mi = 0; mi < 4; mi++)
        #pragma unroll
        for (int ni = 0; ni < 8; ni++)
            #pragma unroll
            for (int j = 0; j < 4; j++) d[mi][ni][j] = 0.f;

    LOAD_STAGE(0, 0);

    for (int kt = 0; kt < ntiles; kt++) {
        asm volatile("cp.async.wait_group 0;" ::: "memory");
        __syncthreads();
        if (kt + 1 < ntiles) {
            if ((kt + 1) & 1) LOAD_STAGE(kt + 1, 1);
            else              LOAD_STAGE(kt + 1, 0);
        }

        const unsigned* as = As[kt & 1];
        const unsigned* bs = Bs[kt & 1];

        #pragma unroll
        for (int ks = 0; ks < 2; ks++) {
            const int c0 = ks * 8 + t;
            unsigned a[4][4], b[8][2];
            #pragma unroll
            for (int mi = 0; mi < 4; mi++) {
                const int m = wm + mi * 16 + g;
                a[mi][0] = as[m * ASTR + c0];
                a[mi][1] = as[(m + 8) * ASTR + c0];
                a[mi][2] = as[m * ASTR + c0 + 4];
                a[mi][3] = as[(m + 8) * ASTR + c0 + 4];
            }
            #pragma unroll
            for (int ni = 0; ni < 8; ni++) {
                const int n = wn + ni * 8 + g;
                b[ni][0] = bs[c0 * BSTR + n];
                b[ni][1] = bs[(c0 + 4) * BSTR + n];
            }
            #pragma unroll
            for (int mi = 0; mi < 4; mi++)
                #pragma unroll
                for (int ni = 0; ni < 8; ni++)
                    mma_tf32(d[mi][ni], a[mi], b[ni]);
        }
    }

    // epilogue: bias + store (optionally tf32-rounded)
    #pragma unroll
    for (int mi = 0; mi < 4; mi++) {
        const int r = row0 + wm + mi * 16 + g;
        #pragma unroll
        for (int ni = 0; ni < 8; ni++) {
            const int c = col0 + wn + ni * 8 + 2 * t;
            const float b0 = bias[c], b1 = bias[c + 1];
            float v00 = d[mi][ni][0] + b0, v01 = d[mi][ni][1] + b1;
            float v10 = d[mi][ni][2] + b0, v11 = d[mi][ni][3] + b1;
            if (ROUND) {
                v00 = __uint_as_float(f2tf32(v00));
                v01 = __uint_as_float(f2tf32(v01));
                v10 = __uint_as_float(f2tf32(v10));
                v11 = __uint_as_float(f2tf32(v11));
            }
            *(float2*)&out[(size_t)r * N + c]       = make_float2(v00, v01);
            *(float2*)&out[(size_t)(r + 8) * N + c] = make_float2(v10, v11);
        }
    }
    #undef LOAD_STAGE
}

// ---------------------------------------------------------------------------
// Tensor-core flash attention v2 (unchanged; 905us-verified).
// ---------------------------------------------------------------------------
#define KSTR 68
#define VSTR 72
#define ATTN_SMEM ((2 * 64 * KSTR + 2 * 64 * VSTR) * 4)

__global__ __launch_bounds__(256, 2)
void attn_tc2_kernel(const float* __restrict__ qkv, float* __restrict__ out)
{
    unsigned* base = (unsigned*)dynsmem;
    unsigned* Kbuf[2];
    unsigned* Vbuf[2];
    Kbuf[0] = base;
    Kbuf[1] = Kbuf[0] + 64 * KSTR;
    Vbuf[0] = Kbuf[1] + 64 * KSTR;
    Vbuf[1] = Vbuf[0] + 64 * VSTR;

    const int bh  = blockIdx.y;
    const int b   = bh >> 4;
    const int h   = bh & 15;
    const int q0  = (gridDim.x - 1 - blockIdx.x) * 128;
    const int tid = threadIdx.x;
    const int lane = tid & 31;
    const int warp = tid >> 5;
    const int g = lane >> 2;
    const int t = lane & 3;

    const size_t rstr = 3 * CC;

    const int st_row[4] = { (tid + 0) >> 4, (tid + 256) >> 4, (tid + 512) >> 4, (tid + 768) >> 4 };
    const int st_c = (tid & 15) * 4;

    #define STAGE_KV(it, slot) do {                                                        \
        const int kvr = (it) * 64;                                                         \
        _Pragma("unroll")                                                                  \
        for (int i_ = 0; i_ < 4; i_++) {                                                   \
            const int row_ = st_row[i_];                                                   \
            const float* src_ = qkv + (size_t)(b * TT + kvr + row_) * rstr + CC + h * DD + st_c; \
            cp_async16(&Kbuf[slot][row_ * KSTR + st_c], src_);                             \
            cp_async16(&Vbuf[slot][row_ * VSTR + st_c], src_ + CC);                        \
        }                                                                                  \
        asm volatile("cp.async.commit_group;" ::: "memory");                               \
    } while (0)

    STAGE_KV(0, 0);

    const int r_lo = q0 + warp * 16 + g;
    const int r_hi = r_lo + 8;
    unsigned qa[8][4];
    {
        const float* qlo = qkv + (size_t)(b * TT + r_lo) * rstr + h * DD;
        const float* qhi = qlo + 8 * rstr;
        #pragma unroll
        for (int kk = 0; kk < 8; kk++) {
            qa[kk][0] = __float_as_uint(qlo[kk * 8 + t]     * 0.125f);
            qa[kk][1] = __float_as_uint(qhi[kk * 8 + t]     * 0.125f);
            qa[kk][2] = __float_as_uint(qlo[kk * 8 + t + 4] * 0.125f);
            qa[kk][3] = __float_as_uint(qhi[kk * 8 + t + 4] * 0.125f);
        }
    }

    float o[8][4];
    #pragma unroll
    for (int nt = 0; nt < 8; nt++)
        #pragma unroll
        for (int j = 0; j < 4; j++) o[nt][j] = 0.f;
    float m0 = -CUDART_INF_F, m1 = -CUDART_INF_F;
    float l0 = 0.f, l1 = 0.f;

    const int ntiles = q0 / 64 + 2;
    const int kv_end_w = q0 + warp * 16 + 16;

    for (int it = 0; it < ntiles; it++) {
        const int kv0 = it * 64;
        asm volatile("cp.async.wait_group 0;" ::: "memory");
        __syncthreads();
        if (it + 1 < ntiles) STAGE_KV(it + 1, (it + 1) & 1);

        if (kv0 < kv_end_w) {
            const unsigned* Kc = Kbuf[it & 1];
            const unsigned* Vc = Vbuf[it & 1];

            float s[8][4];
            #pragma unroll
            for (int nt = 0; nt < 8; nt++) {
                s[nt][0] = 0.f; s[nt][1] = 0.f; s[nt][2] = 0.f; s[nt][3] = 0.f;
                #pragma unroll
                for (int kk = 0; kk < 8; kk++) {
                    unsigned bfr[2];
                    bfr[0] = Kc[(nt * 8 + g) * KSTR + kk * 8 + t];
                    bfr[1] = Kc[(nt * 8 + g) * KSTR + kk * 8 + t + 4];
                    mma_tf32(s[nt], qa[kk], bfr);
                }
            }

            if (kv0 + 64 > r_lo) {
                #pragma unroll
                for (int nt = 0; nt < 8; nt++) {
                    const int c0col = kv0 + nt * 8 + 2 * t;
                    if (c0col     > r_lo) s[nt][0] = -CUDART_INF_F;
                    if (c0col + 1 > r_lo) s[nt][1] = -CUDART_INF_F;
                    if (c0col     > r_hi) s[nt][2] = -CUDART_INF_F;
                    if (c0col + 1 > r_hi) s[nt][3] = -CUDART_INF_F;
                }
            }

            float mx0 = -CUDART_INF_F, mx1 = -CUDART_INF_F;
            #pragma unroll
            for (int nt = 0; nt < 8; nt++) {
                mx0 = fmaxf(mx0, fmaxf(s[nt][0], s[nt][1]));
                mx1 = fmaxf(mx1, fmaxf(s[nt][2], s[nt][3]));
            }
            mx0 = fmaxf(mx0, __shfl_xor_sync(0xffffffffu, mx0, 1));
            mx0 = fmaxf(mx0, __shfl_xor_sync(0xffffffffu, mx0, 2));
            mx1 = fmaxf(mx1, __shfl_xor_sync(0xffffffffu, mx1, 1));
            mx1 = fmaxf(mx1, __shfl_xor_sync(0xffffffffu, mx1, 2));

            const float M0 = fmaxf(m0, mx0), M1 = fmaxf(m1, mx1);
            const float cor0 = __expf(m0 - M0), cor1 = __expf(m1 - M1);
            l0 *= cor0; l1 *= cor1;
            #pragma unroll
            for (int nt = 0; nt < 8; nt++) {
                o[nt][0] *= cor0; o[nt][1] *= cor0;
                o[nt][2] *= cor1; o[nt][3] *= cor1;
            }
            m0 = M0; m1 = M1;

            #pragma unroll
            for (int nt = 0; nt < 8; nt++) {
                s[nt][0] = __expf(s[nt][0] - M0);
                s[nt][1] = __expf(s[nt][1] - M0);
                s[nt][2] = __expf(s[nt][2] - M1);
                s[nt][3] = __expf(s[nt][3] - M1);
                l0 += s[nt][0] + s[nt][1];
                l1 += s[nt][2] + s[nt][3];
            }

            const int srcA = (lane & 28) | (t >> 1);
            const int srcB = srcA + 2;
            const bool hi = (t & 1);
            #pragma unroll
            for (int kk = 0; kk < 8; kk++) {
                const float x0 = __shfl_sync(0xffffffffu, s[kk][0], srcA);
                const float x1 = __shfl_sync(0xffffffffu, s[kk][1], srcA);
                const float x2 = __shfl_sync(0xffffffffu, s[kk][2], srcA);
                const float x3 = __shfl_sync(0xffffffffu, s[kk][3], srcA);
                const float y0 = __shfl_sync(0xffffffffu, s[kk][0], srcB);
                const float y1 = __shfl_sync(0xffffffffu, s[kk][1], srcB);
                const float y2 = __shfl_sync(0xffffffffu, s[kk][2], srcB);
                const float y3 = __shfl_sync(0xffffffffu, s[kk][3], srcB);
                unsigned pa[4];
                pa[0] = f2tf32(hi ? x1 : x0);
                pa[1] = f2tf32(hi ? x3 : x2);
                pa[2] = f2tf32(hi ? y1 : y0);
                pa[3] = f2tf32(hi ? y3 : y2);
                #pragma unroll
                for (int nt2 = 0; nt2 < 8; nt2++) {
                    unsigned bfr[2];
                    bfr[0] = Vc[(kk * 8 + t) * VSTR + nt2 * 8 + g];
                    bfr[1] = Vc[(kk * 8 + t + 4) * VSTR + nt2 * 8 + g];
                    mma_tf32(o[nt2], pa, bfr);
                }
            }
        }
        __syncthreads();
    }
    #undef STAGE_KV

    l0 += __shfl_xor_sync(0xffffffffu, l0, 1);
    l0 += __shfl_xor_sync(0xffffffffu, l0, 2);
    l1 += __shfl_xor_sync(0xffffffffu, l1, 1);
    l1 += __shfl_xor_sync(0xffffffffu, l1, 2);
    const float inv0 = 1.f / l0, inv1 = 1.f / l1;

    float* op_lo = out + ((size_t)(b * TT + r_lo)) * CC + h * DD;
    float* op_hi = out + ((size_t)(b * TT + r_hi)) * CC + h * DD;
    #pragma unroll
    for (int nt2 = 0; nt2 < 8; nt2++) {
        const int c = nt2 * 8 + 2 * t;
        float2 vlo = make_float2(__uint_as_float(f2tf32(o[nt2][0] * inv0)),
                                 __uint_as_float(f2tf32(o[nt2][1] * inv0)));
        float2 vhi = make_float2(__uint_as_float(f2tf32(o[nt2][2] * inv1)),
                                 __uint_as_float(f2tf32(o[nt2][3] * inv1)));
        *(float2*)&op_lo[c] = vlo;
        *(float2*)&op_hi[c] = vhi;
    }
}

// ---------------------------------------------------------------------------
// Launch
// ---------------------------------------------------------------------------
extern "C" void kernel_launch(void* const* d_in, const int* in_sizes, int n_in,
                              void* d_out, int out_size)
{
    const float* hidden = (const float*)d_in[0];   // [B,T,C]
    const float* qkv_w  = (const float*)d_in[1];   // [C, 3C]
    const float* qkv_b  = (const float*)d_in[2];   // [3C]
    const float* o_w    = (const float*)d_in[3];   // [C, C]
    const float* o_b    = (const float*)d_in[4];   // [C]
    float* out = (float*)d_out;                    // [B,T,C]

    float *qkv, *attn, *x, *w1, *w2;
    cudaGetSymbolAddress((void**)&qkv,  g_qkv);
    cudaGetSymbolAddress((void**)&attn, g_attn);
    cudaGetSymbolAddress((void**)&x,    g_x);
    cudaGetSymbolAddress((void**)&w1,   g_w1);
    cudaGetSymbolAddress((void**)&w2,   g_w2);

    // 0) pre-convert operands to tf32
    {
        int n4;
        n4 = BTOT * CC / 4;
        cvt_tf32_kernel<<<(n4 + 255) / 256, 256>>>((const float4*)hidden, (float4*)x, n4);
        n4 = CC * 3 * CC / 4;
        cvt_tf32_kernel<<<(n4 + 255) / 256, 256>>>((const float4*)qkv_w, (float4*)w1, n4);
        n4 = CC * CC / 4;
        cvt_tf32_kernel<<<(n4 + 255) / 256, 256>>>((const float4*)o_w, (float4*)w2, n4);
    }
    // 1) QKV projection (output tf32-rounded for the attention kernel)
    {
        cudaFuncSetAttribute(gemm_tf32_v2<true>,
                             cudaFuncAttributeMaxDynamicSharedMemorySize, GEMM_SMEM);
        dim3 grid(3 * CC / 256, BTOT / 128);
        gemm_tf32_v2<true><<<grid, 256, GEMM_SMEM>>>(x, w1, qkv_b, qkv, BTOT, 3 * CC, CC);
    }
    // 2) Causal multi-head attention (tensor cores, cp.async pipelined)
    {
        cudaFuncSetAttribute(attn_tc2_kernel,
                             cudaFuncAttributeMaxDynamicSharedMemorySize, ATTN_SMEM);
        dim3 grid(TT / 128, BB * HH);
        attn_tc2_kernel<<<grid, 256, ATTN_SMEM>>>(qkv, attn);
    }
    // 3) Output projection (full fp32 output)
    {
        cudaFuncSetAttribute(gemm_tf32_v2<false>,
                             cudaFuncAttributeMaxDynamicSharedMemorySize, GEMM_SMEM);
        dim3 grid(CC / 256, BTOT / 128);
        gemm_tf32_v2<false><<<grid, 256, GEMM_SMEM>>>(attn, w2, o_b, out, BTOT, CC, CC);
    }
}

// round 17
// speedup vs baseline: 1.0382x; 1.0382x over previous
#include <cuda_runtime.h>
#include <math_constants.h>
#include <cstdint>

#define BB 4
#define TT 2048
#define CC 1024
#define HH 16
#define DD 64
#define BTOT (BB*TT)          // 8192 rows

// Scratch (allocation-free rule: __device__ globals)
__device__ float g_qkv[(size_t)BTOT * 3 * CC];   // [B*T, 3C]  (tf32-rounded)
__device__ float g_attn[(size_t)BTOT * CC];      // [B*T, C]   (tf32-rounded)
__device__ float g_x [(size_t)BTOT * CC];        // hidden, tf32-rounded
__device__ float g_w1[(size_t)CC * 3 * CC];      // qkv_w, tf32-rounded
__device__ float g_w2[(size_t)CC * CC];          // o_w, tf32-rounded

extern __shared__ char dynsmem[];

__device__ __forceinline__ unsigned f2tf32(float x) {
    unsigned y;
    asm("cvt.rna.tf32.f32 %0, %1;" : "=r"(y) : "f"(x));
    return y;
}

__device__ __forceinline__ void mma_tf32(float d[4], const unsigned a[4], const unsigned b[2]) {
    asm volatile(
        "mma.sync.aligned.m16n8k8.row.col.f32.tf32.tf32.f32 "
        "{%0,%1,%2,%3}, {%4,%5,%6,%7}, {%8,%9}, {%0,%1,%2,%3};"
        : "+f"(d[0]), "+f"(d[1]), "+f"(d[2]), "+f"(d[3])
        : "r"(a[0]), "r"(a[1]), "r"(a[2]), "r"(a[3]), "r"(b[0]), "r"(b[1]));
}

__device__ __forceinline__ void cp_async16(void* smem_dst, const void* gsrc) {
    unsigned sa = (unsigned)__cvta_generic_to_shared(smem_dst);
    asm volatile("cp.async.ca.shared.global [%0], [%1], 16;" :: "r"(sa), "l"(gsrc));
}

// ---------------------------------------------------------------------------
// Pre-pass: fp32 -> tf32-rounded fp32 (vectorized)
// ---------------------------------------------------------------------------
__global__ void cvt_tf32_kernel(const float4* __restrict__ in, float4* __restrict__ out, int n4)
{
    int i = blockIdx.x * blockDim.x + threadIdx.x;
    if (i < n4) {
        float4 v = in[i];
        uint4 r;
        r.x = f2tf32(v.x); r.y = f2tf32(v.y);
        r.z = f2tf32(v.z); r.w = f2tf32(v.w);
        *(uint4*)&out[i] = r;
    }
}

// ---------------------------------------------------------------------------
// TF32 GEMM v3: 128x128 block tile, BK=16, 128 threads (4 warps, 2x2 grid),
// 64x64 warp tile. 2 blocks/SM (two independent barrier domains) — fat warp
// tile for low crossbar bytes/FLOP, dual blocks for latency hiding.
// out[M,N] = A[M,K] @ W[K,N] + bias[N].  M%128==0, N%128==0, K%16==0.
// A smem row-major stride 20 (banks 20g+t), B k-major stride 136 (8t+g).
// Dynamic smem: 2*(128*20 + 16*136)*4 = 37,888 B.
// ---------------------------------------------------------------------------
#define ASTR 20
#define BSTR 136
#define GEMM_SMEM (2 * (128 * ASTR + 16 * BSTR) * 4)

template<bool ROUND>
__global__ __launch_bounds__(128, 2)
void gemm_tf32_v3(const float* __restrict__ A, const float* __restrict__ W,
                  const float* __restrict__ bias, float* __restrict__ out,
                  int M, int N, int K)
{
    unsigned* As[2];
    unsigned* Bs[2];
    As[0] = (unsigned*)dynsmem;
    As[1] = As[0] + 128 * ASTR;
    Bs[0] = As[1] + 128 * ASTR;
    Bs[1] = Bs[0] + 16 * BSTR;

    const int tid  = threadIdx.x;
    const int lane = tid & 31;
    const int warp = tid >> 5;
    const int g = lane >> 2;
    const int t = lane & 3;
    const int row0 = blockIdx.y * 128;
    const int col0 = blockIdx.x * 128;

    const int wm = (warp >> 1) * 64;    // 0 or 64
    const int wn = (warp & 1) * 64;     // 0 or 64

    const int ntiles = K >> 4;

    // A tile 128x16 = 512 chunks of 16B -> 4/thread; B tile 16x128 -> 4/thread
    const int a_row = tid >> 2, a_kc = (tid & 3) * 4;   // rows 0..31 (+32,+64,+96)
    const int b_row = tid >> 5, b_c  = (tid & 31) * 4;  // rows 0..3 (+4,+8,+12)

    #define LOAD_STAGE(kt, slot) do {                                              \
        const int k0_ = (kt) << 4;                                                 \
        _Pragma("unroll")                                                          \
        for (int i_ = 0; i_ < 4; i_++) {                                           \
            const int ar_ = a_row + 32 * i_;                                       \
            cp_async16(&As[slot][ar_ * ASTR + a_kc],                               \
                       A + (size_t)(row0 + ar_) * K + k0_ + a_kc);                 \
            const int br_ = b_row + 4 * i_;                                        \
            cp_async16(&Bs[slot][br_ * BSTR + b_c],                                \
                       W + (size_t)(k0_ + br_) * N + col0 + b_c);                  \
        }                                                                          \
        asm volatile("cp.async.commit_group;" ::: "memory");                       \
    } while (0)

    float d[4][8][4];
    #pragma unroll
    for (int mi = 0; mi < 4; mi++)
        #pragma unroll
        for (int ni = 0; ni < 8; ni++)
            #pragma unroll
            for (int j = 0; j < 4; j++) d[mi][ni][j] = 0.f;

    LOAD_STAGE(0, 0);

    for (int kt = 0; kt < ntiles; kt++) {
        asm volatile("cp.async.wait_group 0;" ::: "memory");
        __syncthreads();
        if (kt + 1 < ntiles) {
            if ((kt + 1) & 1) LOAD_STAGE(kt + 1, 1);
            else              LOAD_STAGE(kt + 1, 0);
        }

        const unsigned* as = As[kt & 1];
        const unsigned* bs = Bs[kt & 1];

        #pragma unroll
        for (int ks = 0; ks < 2; ks++) {
            const int c0 = ks * 8 + t;
            unsigned a[4][4], b[8][2];
            #pragma unroll
            for (int mi = 0; mi < 4; mi++) {
                const int m = wm + mi * 16 + g;
                a[mi][0] = as[m * ASTR + c0];
                a[mi][1] = as[(m + 8) * ASTR + c0];
                a[mi][2] = as[m * ASTR + c0 + 4];
                a[mi][3] = as[(m + 8) * ASTR + c0 + 4];
            }
            #pragma unroll
            for (int ni = 0; ni < 8; ni++) {
                const int n = wn + ni * 8 + g;
                b[ni][0] = bs[c0 * BSTR + n];
                b[ni][1] = bs[(c0 + 4) * BSTR + n];
            }
            #pragma unroll
            for (int mi = 0; mi < 4; mi++)
                #pragma unroll
                for (int ni = 0; ni < 8; ni++)
                    mma_tf32(d[mi][ni], a[mi], b[ni]);
        }
    }

    // epilogue: bias + store (optionally tf32-rounded)
    #pragma unroll
    for (int mi = 0; mi < 4; mi++) {
        const int r = row0 + wm + mi * 16 + g;
        #pragma unroll
        for (int ni = 0; ni < 8; ni++) {
            const int c = col0 + wn + ni * 8 + 2 * t;
            const float b0 = bias[c], b1 = bias[c + 1];
            float v00 = d[mi][ni][0] + b0, v01 = d[mi][ni][1] + b1;
            float v10 = d[mi][ni][2] + b0, v11 = d[mi][ni][3] + b1;
            if (ROUND) {
                v00 = __uint_as_float(f2tf32(v00));
                v01 = __uint_as_float(f2tf32(v01));
                v10 = __uint_as_float(f2tf32(v10));
                v11 = __uint_as_float(f2tf32(v11));
            }
            *(float2*)&out[(size_t)r * N + c]       = make_float2(v00, v01);
            *(float2*)&out[(size_t)(r + 8) * N + c] = make_float2(v10, v11);
        }
    }
    #undef LOAD_STAGE
}

// ---------------------------------------------------------------------------
// Tensor-core flash attention v2 (unchanged; 905us-verified).
// ---------------------------------------------------------------------------
#define KSTR 68
#define VSTR 72
#define ATTN_SMEM ((2 * 64 * KSTR + 2 * 64 * VSTR) * 4)

__global__ __launch_bounds__(256, 2)
void attn_tc2_kernel(const float* __restrict__ qkv, float* __restrict__ out)
{
    unsigned* base = (unsigned*)dynsmem;
    unsigned* Kbuf[2];
    unsigned* Vbuf[2];
    Kbuf[0] = base;
    Kbuf[1] = Kbuf[0] + 64 * KSTR;
    Vbuf[0] = Kbuf[1] + 64 * KSTR;
    Vbuf[1] = Vbuf[0] + 64 * VSTR;

    const int bh  = blockIdx.y;
    const int b   = bh >> 4;
    const int h   = bh & 15;
    const int q0  = (gridDim.x - 1 - blockIdx.x) * 128;
    const int tid = threadIdx.x;
    const int lane = tid & 31;
    const int warp = tid >> 5;
    const int g = lane >> 2;
    const int t = lane & 3;

    const size_t rstr = 3 * CC;

    const int st_row[4] = { (tid + 0) >> 4, (tid + 256) >> 4, (tid + 512) >> 4, (tid + 768) >> 4 };
    const int st_c = (tid & 15) * 4;

    #define STAGE_KV(it, slot) do {                                                        \
        const int kvr = (it) * 64;                                                         \
        _Pragma("unroll")                                                                  \
        for (int i_ = 0; i_ < 4; i_++) {                                                   \
            const int row_ = st_row[i_];                                                   \
            const float* src_ = qkv + (size_t)(b * TT + kvr + row_) * rstr + CC + h * DD + st_c; \
            cp_async16(&Kbuf[slot][row_ * KSTR + st_c], src_);                             \
            cp_async16(&Vbuf[slot][row_ * VSTR + st_c], src_ + CC);                        \
        }                                                                                  \
        asm volatile("cp.async.commit_group;" ::: "memory");                               \
    } while (0)

    STAGE_KV(0, 0);

    const int r_lo = q0 + warp * 16 + g;
    const int r_hi = r_lo + 8;
    unsigned qa[8][4];
    {
        const float* qlo = qkv + (size_t)(b * TT + r_lo) * rstr + h * DD;
        const float* qhi = qlo + 8 * rstr;
        #pragma unroll
        for (int kk = 0; kk < 8; kk++) {
            qa[kk][0] = __float_as_uint(qlo[kk * 8 + t]     * 0.125f);
            qa[kk][1] = __float_as_uint(qhi[kk * 8 + t]     * 0.125f);
            qa[kk][2] = __float_as_uint(qlo[kk * 8 + t + 4] * 0.125f);
            qa[kk][3] = __float_as_uint(qhi[kk * 8 + t + 4] * 0.125f);
        }
    }

    float o[8][4];
    #pragma unroll
    for (int nt = 0; nt < 8; nt++)
        #pragma unroll
        for (int j = 0; j < 4; j++) o[nt][j] = 0.f;
    float m0 = -CUDART_INF_F, m1 = -CUDART_INF_F;
    float l0 = 0.f, l1 = 0.f;

    const int ntiles = q0 / 64 + 2;
    const int kv_end_w = q0 + warp * 16 + 16;

    for (int it = 0; it < ntiles; it++) {
        const int kv0 = it * 64;
        asm volatile("cp.async.wait_group 0;" ::: "memory");
        __syncthreads();
        if (it + 1 < ntiles) STAGE_KV(it + 1, (it + 1) & 1);

        if (kv0 < kv_end_w) {
            const unsigned* Kc = Kbuf[it & 1];
            const unsigned* Vc = Vbuf[it & 1];

            float s[8][4];
            #pragma unroll
            for (int nt = 0; nt < 8; nt++) {
                s[nt][0] = 0.f; s[nt][1] = 0.f; s[nt][2] = 0.f; s[nt][3] = 0.f;
                #pragma unroll
                for (int kk = 0; kk < 8; kk++) {
                    unsigned bfr[2];
                    bfr[0] = Kc[(nt * 8 + g) * KSTR + kk * 8 + t];
                    bfr[1] = Kc[(nt * 8 + g) * KSTR + kk * 8 + t + 4];
                    mma_tf32(s[nt], qa[kk], bfr);
                }
            }

            if (kv0 + 64 > r_lo) {
                #pragma unroll
                for (int nt = 0; nt < 8; nt++) {
                    const int c0col = kv0 + nt * 8 + 2 * t;
                    if (c0col     > r_lo) s[nt][0] = -CUDART_INF_F;
                    if (c0col + 1 > r_lo) s[nt][1] = -CUDART_INF_F;
                    if (c0col     > r_hi) s[nt][2] = -CUDART_INF_F;
                    if (c0col + 1 > r_hi) s[nt][3] = -CUDART_INF_F;
                }
            }

            float mx0 = -CUDART_INF_F, mx1 = -CUDART_INF_F;
            #pragma unroll
            for (int nt = 0; nt < 8; nt++) {
                mx0 = fmaxf(mx0, fmaxf(s[nt][0], s[nt][1]));
                mx1 = fmaxf(mx1, fmaxf(s[nt][2], s[nt][3]));
            }
            mx0 = fmaxf(mx0, __shfl_xor_sync(0xffffffffu, mx0, 1));
            mx0 = fmaxf(mx0, __shfl_xor_sync(0xffffffffu, mx0, 2));
            mx1 = fmaxf(mx1, __shfl_xor_sync(0xffffffffu, mx1, 1));
            mx1 = fmaxf(mx1, __shfl_xor_sync(0xffffffffu, mx1, 2));

            const float M0 = fmaxf(m0, mx0), M1 = fmaxf(m1, mx1);
            const float cor0 = __expf(m0 - M0), cor1 = __expf(m1 - M1);
            l0 *= cor0; l1 *= cor1;
            #pragma unroll
            for (int nt = 0; nt < 8; nt++) {
                o[nt][0] *= cor0; o[nt][1] *= cor0;
                o[nt][2] *= cor1; o[nt][3] *= cor1;
            }
            m0 = M0; m1 = M1;

            #pragma unroll
            for (int nt = 0; nt < 8; nt++) {
                s[nt][0] = __expf(s[nt][0] - M0);
                s[nt][1] = __expf(s[nt][1] - M0);
                s[nt][2] = __expf(s[nt][2] - M1);
                s[nt][3] = __expf(s[nt][3] - M1);
                l0 += s[nt][0] + s[nt][1];
                l1 += s[nt][2] + s[nt][3];
            }

            const int srcA = (lane & 28) | (t >> 1);
            const int srcB = srcA + 2;
            const bool hi = (t & 1);
            #pragma unroll
            for (int kk = 0; kk < 8; kk++) {
                const float x0 = __shfl_sync(0xffffffffu, s[kk][0], srcA);
                const float x1 = __shfl_sync(0xffffffffu, s[kk][1], srcA);
                const float x2 = __shfl_sync(0xffffffffu, s[kk][2], srcA);
                const float x3 = __shfl_sync(0xffffffffu, s[kk][3], srcA);
                const float y0 = __shfl_sync(0xffffffffu, s[kk][0], srcB);
                const float y1 = __shfl_sync(0xffffffffu, s[kk][1], srcB);
                const float y2 = __shfl_sync(0xffffffffu, s[kk][2], srcB);
                const float y3 = __shfl_sync(0xffffffffu, s[kk][3], srcB);
                unsigned pa[4];
                pa[0] = f2tf32(hi ? x1 : x0);
                pa[1] = f2tf32(hi ? x3 : x2);
                pa[2] = f2tf32(hi ? y1 : y0);
                pa[3] = f2tf32(hi ? y3 : y2);
                #pragma unroll
                for (int nt2 = 0; nt2 < 8; nt2++) {
                    unsigned bfr[2];
                    bfr[0] = Vc[(kk * 8 + t) * VSTR + nt2 * 8 + g];
                    bfr[1] = Vc[(kk * 8 + t + 4) * VSTR + nt2 * 8 + g];
                    mma_tf32(o[nt2], pa, bfr);
                }
            }
        }
        __syncthreads();
    }
    #undef STAGE_KV

    l0 += __shfl_xor_sync(0xffffffffu, l0, 1);
    l0 += __shfl_xor_sync(0xffffffffu, l0, 2);
    l1 += __shfl_xor_sync(0xffffffffu, l1, 1);
    l1 += __shfl_xor_sync(0xffffffffu, l1, 2);
    const float inv0 = 1.f / l0, inv1 = 1.f / l1;

    float* op_lo = out + ((size_t)(b * TT + r_lo)) * CC + h * DD;
    float* op_hi = out + ((size_t)(b * TT + r_hi)) * CC + h * DD;
    #pragma unroll
    for (int nt2 = 0; nt2 < 8; nt2++) {
        const int c = nt2 * 8 + 2 * t;
        float2 vlo = make_float2(__uint_as_float(f2tf32(o[nt2][0] * inv0)),
                                 __uint_as_float(f2tf32(o[nt2][1] * inv0)));
        float2 vhi = make_float2(__uint_as_float(f2tf32(o[nt2][2] * inv1)),
                                 __uint_as_float(f2tf32(o[nt2][3] * inv1)));
        *(float2*)&op_lo[c] = vlo;
        *(float2*)&op_hi[c] = vhi;
    }
}

// ---------------------------------------------------------------------------
// Launch
// ---------------------------------------------------------------------------
extern "C" void kernel_launch(void* const* d_in, const int* in_sizes, int n_in,
                              void* d_out, int out_size)
{
    const float* hidden = (const float*)d_in[0];   // [B,T,C]
    const float* qkv_w  = (const float*)d_in[1];   // [C, 3C]
    const float* qkv_b  = (const float*)d_in[2];   // [3C]
    const float* o_w    = (const float*)d_in[3];   // [C, C]
    const float* o_b    = (const float*)d_in[4];   // [C]
    float* out = (float*)d_out;                    // [B,T,C]

    float *qkv, *attn, *x, *w1, *w2;
    cudaGetSymbolAddress((void**)&qkv,  g_qkv);
    cudaGetSymbolAddress((void**)&attn, g_attn);
    cudaGetSymbolAddress((void**)&x,    g_x);
    cudaGetSymbolAddress((void**)&w1,   g_w1);
    cudaGetSymbolAddress((void**)&w2,   g_w2);

    // 0) pre-convert operands to tf32
    {
        int n4;
        n4 = BTOT * CC / 4;
        cvt_tf32_kernel<<<(n4 + 255) / 256, 256>>>((const float4*)hidden, (float4*)x, n4);
        n4 = CC * 3 * CC / 4;
        cvt_tf32_kernel<<<(n4 + 255) / 256, 256>>>((const float4*)qkv_w, (float4*)w1, n4);
        n4 = CC * CC / 4;
        cvt_tf32_kernel<<<(n4 + 255) / 256, 256>>>((const float4*)o_w, (float4*)w2, n4);
    }
    // 1) QKV projection (output tf32-rounded for the attention kernel)
    {
        cudaFuncSetAttribute(gemm_tf32_v3<true>,
                             cudaFuncAttributeMaxDynamicSharedMemorySize, GEMM_SMEM);
        dim3 grid(3 * CC / 128, BTOT / 128);
        gemm_tf32_v3<true><<<grid, 128, GEMM_SMEM>>>(x, w1, qkv_b, qkv, BTOT, 3 * CC, CC);
    }
    // 2) Causal multi-head attention (tensor cores, cp.async pipelined)
    {
        cudaFuncSetAttribute(attn_tc2_kernel,
                             cudaFuncAttributeMaxDynamicSharedMemorySize, ATTN_SMEM);
        dim3 grid(TT / 128, BB * HH);
        attn_tc2_kernel<<<grid, 256, ATTN_SMEM>>>(qkv, attn);
    }
    // 3) Output projection (full fp32 output)
    {
        cudaFuncSetAttribute(gemm_tf32_v3<false>,
                             cudaFuncAttributeMaxDynamicSharedMemorySize, GEMM_SMEM);
        dim3 grid(CC / 128, BTOT / 128);
        gemm_tf32_v3<false><<<grid, 128, GEMM_SMEM>>>(attn, w2, o_b, out, BTOT, CC, CC);
    }
}